// round 1
// baseline (speedup 1.0000x reference)
#include <cuda_runtime.h>
#include <cstddef>

// CTC loss, faithful to the reference (including the input_len = C bug):
//   B=512, T=512 (stride only; Tu=128 timesteps used), C=128, L=64
//   S = 2L+1 = 129 extended states, blank = C-1 = 127
// One block per batch element, one thread per extended state.
// Alpha recursion runs in log2 domain (MUFU lg2/ex2 are native single-ops);
// final loss multiplies by ln2. Exactly equivalent math.

#define CTC_B     512
#define CTC_T     512
#define CTC_C     128
#define CTC_L     64
#define CTC_TU    128       // input_len = C (source bug, replicated)
#define CTC_S     129       // 2L+1
#define CTC_BLANK 127
#define NEGF      (-1e30f)
#define EPSF      (1e-7f)
#define LN2F      (0.69314718055994530942f)

__global__ __launch_bounds__(CTC_S, 8)
void ctc_alpha_kernel(const int* __restrict__ y_true,
                      const float* __restrict__ y_pred,
                      float* __restrict__ out)
{
    // state s stored at index s+2; indices 0,1 are permanent NEG pads
    __shared__ float abuf[2][CTC_S + 2];

    const int s = threadIdx.x;          // 0..128
    const int b = blockIdx.x;           // 0..511

    // --- per-state constants -------------------------------------------------
    int lab;
    bool skip;
    if (s & 1) {
        const int li = s >> 1;
        lab  = y_true[b * CTC_L + li];
        // skip allowed iff label != blank (always true here) and != previous label
        skip = (s >= 3) && (lab != y_true[b * CTC_L + li - 1]);
    } else {
        lab  = CTC_BLANK;
        skip = false;
    }

    const float* __restrict__ ptr =
        y_pred + (size_t)b * CTC_T * CTC_C + lab;   // advance by C per timestep

    // --- init (t = 0) --------------------------------------------------------
    if (s < 2) {                 // NEG pads (written once, never touched again)
        abuf[0][s] = NEGF;
        abuf[1][s] = NEGF;
    }
    {
        const float p0 = ptr[0];
        const float a0 = (s < 2) ? __log2f(p0 + EPSF) : NEGF;
        abuf[0][s + 2] = a0;
    }
    __syncthreads();

    // --- recursion t = 1..127 ------------------------------------------------
    int cur = 0;
    float p_cur = ptr[CTC_C];            // t = 1 prefetched
    #pragma unroll 4
    for (int t = 1; t < CTC_TU; ++t) {
        // prefetch next timestep's probability (distance-1)
        const float p_nxt = (t + 1 < CTC_TU) ? ptr[(t + 1) * CTC_C] : 0.0f;

        const float lp2 = __log2f(p_cur + EPSF);

        const float x0 = abuf[cur][s + 2];
        const float x1 = abuf[cur][s + 1];
        const float x2 = skip ? abuf[cur][s] : NEGF;

        const float m   = fmaxf(x0, fmaxf(x1, x2));
        const float sum = exp2f(x0 - m) + exp2f(x1 - m) + exp2f(x2 - m);
        const float na  = m + __log2f(sum) + lp2;

        abuf[cur ^ 1][s + 2] = na;
        __syncthreads();
        cur ^= 1;
        p_cur = p_nxt;
    }

    // --- tail: loss = -ln2 * log2sumexp2(alpha[S-2], alpha[S-1]) -------------
    if (s == 0) {
        const float a  = abuf[cur][CTC_S];       // state 127
        const float c  = abuf[cur][CTC_S + 1];   // state 128
        const float m  = fmaxf(a, c);
        const float l2 = m + __log2f(exp2f(a - m) + exp2f(c - m));
        out[b] = -LN2F * l2;
    }
}

extern "C" void kernel_launch(void* const* d_in, const int* in_sizes, int n_in,
                              void* d_out, int out_size)
{
    // metadata order: y_true (int32, 512*64), y_pred (float32, 512*512*128)
    // pick by size to be robust to ordering
    const int* y_true;
    const float* y_pred;
    if (n_in >= 2 && in_sizes[0] == CTC_B * CTC_L) {
        y_true = (const int*)d_in[0];
        y_pred = (const float*)d_in[1];
    } else {
        y_true = (const int*)d_in[1];
        y_pred = (const float*)d_in[0];
    }
    float* out = (float*)d_out;

    ctc_alpha_kernel<<<CTC_B, CTC_S>>>(y_true, y_pred, out);
}

// round 2
// speedup vs baseline: 2.4513x; 2.4513x over previous
#include <cuda_runtime.h>
#include <cstddef>

// CTC loss (faithful to the reference incl. the input_len = C bug).
// B=512, T=512 (row stride), C=128 classes, Tu=128 used timesteps,
// L=64 labels, S=129 extended states, blank=127.
//
// One WARP per batch row. Lane holds states s = 4*lane + j (j=0..3);
// lane 31 additionally holds state 128 (j=4).
// Recursion runs in the LINEAR domain with power-of-two rescaling every
// 8 steps (exponent tracked as an integer). Only cross-lane value needed
// per step is the neighbor's a3 (state 4*(lane-1)+3 = s-1 for j=0 and
// s-2 for j=1) -> a single shfl_up per timestep. No smem, no barriers,
// no MUFU in the hot loop.

#define B_    512
#define T_    512
#define C_    128
#define L_    64
#define TU    128
#define BLANK 127
#define EPSF  (1e-7f)
#define LN2F  (0.69314718055994530942f)
#define PD    8            // prefetch distance (= rescale period)

__global__ __launch_bounds__(128, 8)
void ctc_warp_kernel(const int* __restrict__ y_true,
                     const float* __restrict__ y_pred,
                     float* __restrict__ out)
{
    const unsigned FULL = 0xffffffffu;
    const int lane = threadIdx.x & 31;
    const int b    = blockIdx.x * 4 + (threadIdx.x >> 5);   // warp-per-row

    const float* __restrict__ row = y_pred + (size_t)b * T_ * C_;
    const int*   __restrict__ lab = y_true + b * L_;

    // this lane's two labels (odd states j=1 -> li=2*lane, j=3 -> li=2*lane+1)
    const int l0 = lab[2 * lane];
    const int l1 = lab[2 * lane + 1];
    const int lp = (lane > 0) ? lab[2 * lane - 1] : -1;
    const bool skip1 = (lane > 0) && (l0 != lp);   // state 4l+1: s-2 = neighbor a3
    const bool skip3 = (l1 != l0);                 // state 4l+3: s-2 = own a1

    const float* __restrict__ p0 = row + l0;
    const float* __restrict__ p1 = row + l1;
    const float* __restrict__ pz = row + BLANK;

    // ---- t = 0 init: alpha[0] = q_blank, alpha[1] = q_label0, else 0 ------
    float a0 = 0.f, a1 = 0.f, a2 = 0.f, a3 = 0.f, a4 = 0.f;
    if (lane == 0) {
        a0 = pz[0] + EPSF;
        a1 = p0[0] + EPSF;
    }

    int etot = 0;   // sum of extracted exponents (alpha_true = alpha * 2^etot)

    // ---- prefetch ring: probabilities for t = 1..PD ------------------------
    float qa[PD], qb[PD], qz[PD];
    #pragma unroll
    for (int j = 0; j < PD; ++j) {
        qa[j] = p0[(j + 1) * C_];
        qb[j] = p1[(j + 1) * C_];
        qz[j] = pz[(j + 1) * C_];
    }

    // ---- main loop: t = 1..120 in 15 chunks of 8, rescale per chunk --------
    for (int c = 0; c < 15; ++c) {
        #pragma unroll
        for (int j = 0; j < PD; ++j) {
            const int t  = 1 + c * PD + j;
            const float q0 = qa[j] + EPSF;
            const float q1 = qb[j] + EPSF;
            const float qB = qz[j] + EPSF;

            const int tp = t + PD;            // prefetch distance-PD ahead
            if (tp < TU) {
                qa[j] = p0[tp * C_];
                qb[j] = p1[tp * C_];
                qz[j] = pz[tp * C_];
            }

            float n3 = __shfl_up_sync(FULL, a3, 1);   // neighbor state 4(l-1)+3
            if (lane == 0) n3 = 0.f;

            const float na0 = (a0 + n3) * qB;                          // s=4l   (blank)
            const float na1 = (a1 + a0 + (skip1 ? n3 : 0.f)) * q0;     // s=4l+1
            const float na2 = (a2 + a1) * qB;                          // s=4l+2 (blank)
            const float na3 = (a3 + a2 + (skip3 ? a1 : 0.f)) * q1;     // s=4l+3
            const float na4 = (a4 + a3) * qB;                          // s=128 (lane31)
            a0 = na0; a1 = na1; a2 = na2; a3 = na3; a4 = na4;
        }
        // power-of-two rescale: uniform across the warp
        float mv = fmaxf(fmaxf(a0, a1), fmaxf(fmaxf(a2, a3), a4));
        #pragma unroll
        for (int k = 16; k >= 1; k >>= 1)
            mv = fmaxf(mv, __shfl_xor_sync(FULL, mv, k));
        const int   e  = (__float_as_int(mv) >> 23) - 127;
        const float sc = __int_as_float((127 - e) << 23);   // 2^-e
        a0 *= sc; a1 *= sc; a2 *= sc; a3 *= sc; a4 *= sc;
        etot += e;
    }

    // ---- tail: t = 121..127 (ring slots j = 0..6 hold them) ----------------
    #pragma unroll
    for (int j = 0; j < 7; ++j) {
        const float q0 = qa[j] + EPSF;
        const float q1 = qb[j] + EPSF;
        const float qB = qz[j] + EPSF;

        float n3 = __shfl_up_sync(FULL, a3, 1);
        if (lane == 0) n3 = 0.f;

        const float na0 = (a0 + n3) * qB;
        const float na1 = (a1 + a0 + (skip1 ? n3 : 0.f)) * q0;
        const float na2 = (a2 + a1) * qB;
        const float na3 = (a3 + a2 + (skip3 ? a1 : 0.f)) * q1;
        const float na4 = (a4 + a3) * qB;
        a0 = na0; a1 = na1; a2 = na2; a3 = na3; a4 = na4;
    }

    // ---- loss = -ln(alpha[127] + alpha[128]) - etot*ln2 --------------------
    if (lane == 31) {
        const float s = a3 + a4;        // states 127 (a3) and 128 (a4)
        out[b] = -(__logf(s) + (float)etot * LN2F);
    }
}

extern "C" void kernel_launch(void* const* d_in, const int* in_sizes, int n_in,
                              void* d_out, int out_size)
{
    const int* y_true;
    const float* y_pred;
    if (n_in >= 2 && in_sizes[0] == B_ * L_) {
        y_true = (const int*)d_in[0];
        y_pred = (const float*)d_in[1];
    } else {
        y_true = (const int*)d_in[1];
        y_pred = (const float*)d_in[0];
    }
    float* out = (float*)d_out;

    // 4 warps per block (one per SMSP), 128 blocks -> 512 rows
    ctc_warp_kernel<<<B_ / 4, 128>>>(y_true, y_pred, out);
}